// round 6
// baseline (speedup 1.0000x reference)
#include <cuda_runtime.h>
#include <math.h>

// Fused RoPE, positions == arange(S) (reference overwrites token_positions).
//   out[b,s,2k]   = cos(s*w_k)*x[b,s,2k] - sin(s*w_k)*x[b,s,2k+1]
//   out[b,s,2k+1] = sin(s*w_k)*x[b,s,2k] + cos(s*w_k)*x[b,s,2k+1]
//   w_k = 10000^(-k/64) = exp2(-k*log2(10000)/64)
//
// R5: 17.57us, occ 59.6% (38 regs / 6 CTAs/SM). This round: force 32 regs
// via __launch_bounds__(256, 8) -> 8 CTAs/SM, keeping 4 front-batched
// LDG.128 (MLP=4) with compile-time-constant offsets so one 64-bit base
// register serves all 8 memory ops. __stcs stores keep `out` (never re-read)
// from evicting x's L2 residency across graph replays.

#define BATCH   32
#define SEQ     4096
#define DK      128
#define QUADS   (DK / 4)            // 32 float4 per row
#define COLS    (SEQ * QUADS)       // 131072 (s,q) columns
#define BGROUP  4                   // batches per thread
#define NGROUPS (BATCH / BGROUP)    // 8

__global__ void __launch_bounds__(256, 8) rope_fused(
        const float4* __restrict__ x, float4* __restrict__ out) {
    int idx = blockIdx.x * blockDim.x + threadIdx.x;   // 0 .. COLS*NGROUPS-1
    int col = idx & (COLS - 1);      // s*QUADS + q
    int g   = idx >> 17;             // batch group 0..7
    int q = col & (QUADS - 1);
    int s = col >> 5;

    const float4* xp = x   + (size_t)col + (size_t)g * (BGROUP * COLS);
    float4*       op = out + (size_t)col + (size_t)g * (BGROUP * COLS);

    // Issue all 4 loads first (imm offsets): MLP=4, trig hides under latency.
    float4 v0 = xp[0];
    float4 v1 = xp[COLS];
    float4 v2 = xp[2 * COLS];
    float4 v3 = xp[3 * COLS];

    // -log2(10000)/64
    const float C = -0.2076205059304601f;
    float a0 = (float)s * exp2f((float)(2 * q)     * C);
    float a1 = (float)s * exp2f((float)(2 * q + 1) * C);

    float s0, c0, s1, c1;
    sincosf(a0, &s0, &c0);
    sincosf(a1, &s1, &c1);

    float4 r;
    r.x = c0 * v0.x - s0 * v0.y;
    r.y = s0 * v0.x + c0 * v0.y;
    r.z = c1 * v0.z - s1 * v0.w;
    r.w = s1 * v0.z + c1 * v0.w;
    __stcs(op, r);

    r.x = c0 * v1.x - s0 * v1.y;
    r.y = s0 * v1.x + c0 * v1.y;
    r.z = c1 * v1.z - s1 * v1.w;
    r.w = s1 * v1.z + c1 * v1.w;
    __stcs(op + COLS, r);

    r.x = c0 * v2.x - s0 * v2.y;
    r.y = s0 * v2.x + c0 * v2.y;
    r.z = c1 * v2.z - s1 * v2.w;
    r.w = s1 * v2.z + c1 * v2.w;
    __stcs(op + 2 * COLS, r);

    r.x = c0 * v3.x - s0 * v3.y;
    r.y = s0 * v3.x + c0 * v3.y;
    r.z = c1 * v3.z - s1 * v3.w;
    r.w = s1 * v3.z + c1 * v3.w;
    __stcs(op + 3 * COLS, r);
}

extern "C" void kernel_launch(void* const* d_in, const int* in_sizes, int n_in,
                              void* d_out, int out_size) {
    const float* x = (const float*)d_in[0];
    // d_in[1] = token_positions (unused: reference overwrites with arange)
    // d_in[2] = rot (unused: trig recomputed on device)

    int threads = 256;
    int total = COLS * NGROUPS;                  // 1,048,576 threads
    rope_fused<<<total / threads, threads>>>((const float4*)x, (float4*)d_out);
}

// round 7
// speedup vs baseline: 1.0965x; 1.0965x over previous
#include <cuda_runtime.h>
#include <math.h>

// Fused RoPE, positions == arange(S) (reference overwrites token_positions).
//   out[b,s,2k]   = cos(s*w_k)*x[b,s,2k] - sin(s*w_k)*x[b,s,2k+1]
//   out[b,s,2k+1] = sin(s*w_k)*x[b,s,2k] + cos(s*w_k)*x[b,s,2k+1]
//   w_k = 10000^(-k/64) = exp2(-k*log2(10000)/64)
//
// R6 post-mortem: forcing 32 regs de-batched the loads (MLP 4 -> ~1) and
// regressed despite 95% occ. Binding resource = warps x MLP (outstanding
// loads), not occupancy. This round: BGROUP=8, 8 front-batched LDG.128
// (MLP=8), no min-blocks clamp; ~4 CTAs/SM x MLP8 > R5's 6 CTAs x MLP4.

#define BATCH   32
#define SEQ     4096
#define DK      128
#define QUADS   (DK / 4)            // 32 float4 per row
#define COLS    (SEQ * QUADS)       // 131072 (s,q) columns
#define BGROUP  8                   // batches per thread
#define NGROUPS (BATCH / BGROUP)    // 4

__global__ void __launch_bounds__(256) rope_fused(
        const float4* __restrict__ x, float4* __restrict__ out) {
    int idx = blockIdx.x * blockDim.x + threadIdx.x;   // 0 .. COLS*NGROUPS-1
    int col = idx & (COLS - 1);      // s*QUADS + q
    int g   = idx >> 17;             // batch group 0..3
    int q = col & (QUADS - 1);
    int s = col >> 5;

    const float4* xp = x   + (size_t)col + (size_t)g * (BGROUP * COLS);
    float4*       op = out + (size_t)col + (size_t)g * (BGROUP * COLS);

    // Front-batch all 8 loads (imm offsets): MLP=8, trig hides under latency.
    float4 v0 = xp[0];
    float4 v1 = xp[COLS];
    float4 v2 = xp[2 * COLS];
    float4 v3 = xp[3 * COLS];
    float4 v4 = xp[4 * COLS];
    float4 v5 = xp[5 * COLS];
    float4 v6 = xp[6 * COLS];
    float4 v7 = xp[7 * COLS];

    // -log2(10000)/64
    const float C = -0.2076205059304601f;
    float a0 = (float)s * exp2f((float)(2 * q)     * C);
    float a1 = (float)s * exp2f((float)(2 * q + 1) * C);

    float s0, c0, s1, c1;
    sincosf(a0, &s0, &c0);
    sincosf(a1, &s1, &c1);

    float4 r;
#define ROT_STORE(V, OFF)                      \
    r.x = c0 * (V).x - s0 * (V).y;             \
    r.y = s0 * (V).x + c0 * (V).y;             \
    r.z = c1 * (V).z - s1 * (V).w;             \
    r.w = s1 * (V).z + c1 * (V).w;             \
    __stcs(op + (OFF), r)

    ROT_STORE(v0, 0);
    ROT_STORE(v1, COLS);
    ROT_STORE(v2, 2 * COLS);
    ROT_STORE(v3, 3 * COLS);
    ROT_STORE(v4, 4 * COLS);
    ROT_STORE(v5, 5 * COLS);
    ROT_STORE(v6, 6 * COLS);
    ROT_STORE(v7, 7 * COLS);
#undef ROT_STORE
}

extern "C" void kernel_launch(void* const* d_in, const int* in_sizes, int n_in,
                              void* d_out, int out_size) {
    const float* x = (const float*)d_in[0];
    // d_in[1] = token_positions (unused: reference overwrites with arange)
    // d_in[2] = rot (unused: trig recomputed on device)

    int threads = 256;
    int total = COLS * NGROUPS;                  // 524,288 threads
    rope_fused<<<total / threads, threads>>>((const float4*)x, (float4*)d_out);
}

// round 8
// speedup vs baseline: 1.1099x; 1.0122x over previous
#include <cuda_runtime.h>
#include <math.h>

// Fused RoPE, positions == arange(S) (reference overwrites token_positions).
//   out[b,s,2k]   = cos(s*w_k)*x[b,s,2k] - sin(s*w_k)*x[b,s,2k+1]
//   out[b,s,2k+1] = sin(s*w_k)*x[b,s,2k] + cos(s*w_k)*x[b,s,2k+1]
//   w_k = 10000^(-k/64) = exp2(-k*log2(10000)/64)
//
// R7 post-mortem: MLP=8 @ 256-thr blocks -> 53 regs -> only ~26 warps/SM and
// a 2048-CTA tail-heavy grid; neutral vs R5. This round: same MLP=8 body but
// 128-thread blocks -> 9 CTAs/SM (36 warps, 75% occ) and 4096 CTAs.
// warps x MLP ~ 288/SM, the highest of any config so far.

#define BATCH   32
#define SEQ     4096
#define DK      128
#define QUADS   (DK / 4)            // 32 float4 per row
#define COLS    (SEQ * QUADS)       // 131072 (s,q) columns
#define BGROUP  8                   // batches per thread
#define NGROUPS (BATCH / BGROUP)    // 4
#define TPB     128

__global__ void __launch_bounds__(TPB) rope_fused(
        const float4* __restrict__ x, float4* __restrict__ out) {
    int idx = blockIdx.x * blockDim.x + threadIdx.x;   // 0 .. COLS*NGROUPS-1
    int col = idx & (COLS - 1);      // s*QUADS + q
    int g   = idx >> 17;             // batch group 0..3
    int q = col & (QUADS - 1);
    int s = col >> 5;

    const float4* xp = x   + (size_t)col + (size_t)g * (BGROUP * COLS);
    float4*       op = out + (size_t)col + (size_t)g * (BGROUP * COLS);

    // Front-batch all 8 loads (imm offsets): MLP=8, trig hides under latency.
    float4 v0 = xp[0];
    float4 v1 = xp[COLS];
    float4 v2 = xp[2 * COLS];
    float4 v3 = xp[3 * COLS];
    float4 v4 = xp[4 * COLS];
    float4 v5 = xp[5 * COLS];
    float4 v6 = xp[6 * COLS];
    float4 v7 = xp[7 * COLS];

    // -log2(10000)/64
    const float C = -0.2076205059304601f;
    float a0 = (float)s * exp2f((float)(2 * q)     * C);
    float a1 = (float)s * exp2f((float)(2 * q + 1) * C);

    float s0, c0, s1, c1;
    sincosf(a0, &s0, &c0);
    sincosf(a1, &s1, &c1);

    float4 r;
#define ROT_STORE(V, OFF)                      \
    r.x = c0 * (V).x - s0 * (V).y;             \
    r.y = s0 * (V).x + c0 * (V).y;             \
    r.z = c1 * (V).z - s1 * (V).w;             \
    r.w = s1 * (V).z + c1 * (V).w;             \
    __stcs(op + (OFF), r)

    ROT_STORE(v0, 0);
    ROT_STORE(v1, COLS);
    ROT_STORE(v2, 2 * COLS);
    ROT_STORE(v3, 3 * COLS);
    ROT_STORE(v4, 4 * COLS);
    ROT_STORE(v5, 5 * COLS);
    ROT_STORE(v6, 6 * COLS);
    ROT_STORE(v7, 7 * COLS);
#undef ROT_STORE
}

extern "C" void kernel_launch(void* const* d_in, const int* in_sizes, int n_in,
                              void* d_out, int out_size) {
    const float* x = (const float*)d_in[0];
    // d_in[1] = token_positions (unused: reference overwrites with arange)
    // d_in[2] = rot (unused: trig recomputed on device)

    int total = COLS * NGROUPS;                  // 524,288 threads
    rope_fused<<<total / TPB, TPB>>>((const float4*)x, (float4*)d_out);
}